// round 15
// baseline (speedup 1.0000x reference)
#include <cuda_runtime.h>

// Problem constants
#define BATCH 8
#define IMH 180
#define IMW 180
#define NF 24
#define NB 31
#define NPIX (IMH * IMW)          // 32400
#define NTOT (BATCH * NPIX)       // 259200
#define N4   (NTOT / 4)           // 64800

#define TILE 32
#define UT 40                      // u tile rows (TILE + 2*4)
#define PT 36                      // phi tile rows (TILE + 2*2)
#define RS 44                      // padded row stride (words): conflict-free phases

// LUT for phi(x); nearest-knot + centered slope, magic-number index
#define NCELL 1024
#define XMIN (-2.0f)
#define XMAX (2.0f)
#define LUT_H ((XMAX - XMIN) / (float)NCELL)
#define LUT_INVH ((float)NCELL / (XMAX - XMIN))
#define MAGICF 12582912.0f         // 1.5 * 2^23
#define MAGICI 0x4B400000

#define NTHR 384                   // 3 filter-groups of 128 threads
#define NFG  8                     // filters per group

__device__ float  g_partials[64];
__device__ float2 g_lut[NCELL];

// ---------------------------------------------------------------------------
// k_init: blocks [0,4) build the LUT (value at knot, centered slope);
// blocks [4,68) weighted partial sums for M.
// ---------------------------------------------------------------------------
__global__ void k_init(const float* __restrict__ u,
                       const float* __restrict__ mu,
                       const float* __restrict__ wts) {
    const int tid = threadIdx.x;
    if (blockIdx.x < 4) {
        int i = blockIdx.x * 256 + tid;        // 0..1023
        float xc = XMIN + (float)i * LUT_H;
        float pm = 0.f, p0 = 0.f, pp = 0.f;
        #pragma unroll 1
        for (int j = 0; j < NB; j++) {
            float m = mu[j], w = wts[j];
            float dm = xc - LUT_H - m, d0 = xc - m, dp = xc + LUT_H - m;
            pm += w * expf(-50.f * dm * dm);
            p0 += w * expf(-50.f * d0 * d0);
            pp += w * expf(-50.f * dp * dp);
        }
        g_lut[i] = make_float2(p0, 0.5f * (pp - pm));
    } else {
        __shared__ float sm[256];
        const int pb = blockIdx.x - 4;         // 0..63
        float s = 0.f;
        for (int i = pb * 256 + tid; i < N4; i += 64 * 256) {
            int idx4 = i * 4;
            int p = idx4 % NPIX;
            int y = p / IMW;
            int x0 = p - y * IMW;
            float wy = 3.f - (y == 0 ? 1.f : 0.f) - (y == IMH - 1 ? 1.f : 0.f);
            float4 v = ((const float4*)u)[i];
            float w0 = (x0 == 0) ? 2.f : 3.f;
            float w3 = (x0 == IMW - 4) ? 2.f : 3.f;
            s += wy * (v.x * w0 + v.y * 3.f + v.z * 3.f + v.w * w3);
        }
        sm[tid] = s;
        __syncthreads();
        for (int o = 128; o > 0; o >>= 1) {
            if (tid < o) sm[tid] += sm[tid + o];
            __syncthreads();
        }
        if (tid == 0) g_partials[pb] = sm[0];
    }
}

// ---------------------------------------------------------------------------
// k_main: fused TNRD stage per 32x32 tile; 3 filter-groups of 128 threads.
// Per filter: load F[25] into registers (7 x LDS.128), then
//   FWD (dy-major, each of 7 u rows loaded ONCE) -> phi buffer ; bar ;
//   ADJ (dy-major, each of 6 phi rows loaded ONCE, taps = same F flipped) ; bar
// All 2-D tiles use the 44-word padded stride (bank-disjoint phases).
// Dynamic smem layout (bytes):
//   [0, 8192)        sLUT : 1024 x float2
//   [8192, 15232)    sU   : 40 rows x 44 stride
//   [15232, 21568)   sUS  : 36 rows x 44 stride
//   [21568, 40576)   sPhi : 3 buffers of 36 x 44 (one per group)
//   [40576, 43264)   sF   : 24 filters x 28 floats (25 taps + 3 pad)
// ---------------------------------------------------------------------------
#define OFF_LUT 0
#define OFF_U   8192
#define OFF_US  15232
#define OFF_PHI 21568
#define OFF_F   40576
#define PHI_STRIDE (PT * RS * 4)   // 6336 bytes
#define SMEM_BYTES 43264

__global__ __launch_bounds__(NTHR, 2) void k_main(
    const float* __restrict__ u,
    const float* __restrict__ f,
    const float* __restrict__ filt,
    const float* __restrict__ lam,
    float* __restrict__ out)
{
    extern __shared__ char smem[];
    float2* sLUT = (float2*)(smem + OFF_LUT);
    float*  sU   = (float*)(smem + OFF_U);
    float*  sUS  = (float*)(smem + OFF_US);
    float*  sF   = (float*)(smem + OFF_F);
    __shared__ float s_invM;

    const int b   = blockIdx.z;
    const int oy0 = blockIdx.y * TILE;
    const int ox0 = blockIdx.x * TILE;
    const int tid = threadIdx.x;
    const int g   = tid / 128;         // filter-group 0..2
    const int gt  = tid - g * 128;     // lane within group

    const float* ub = u + b * NPIX;
    const float* fb = f + b * NPIX;
    float* ob = out + b * NPIX;

    float* phiBuf = (float*)(smem + OFF_PHI + g * PHI_STRIDE);

    // ---- invM: single-warp shuffle reduction over 64 partials ----
    if (tid < 32) {
        float s = g_partials[tid] + g_partials[tid + 32];
        #pragma unroll
        for (int o = 16; o > 0; o >>= 1)
            s += __shfl_down_sync(0xffffffffu, s, o);
        if (tid == 0)
            s_invM = 1.f / (s / (9.f * (float)NTOT) + 0.001f);
    }

    // ---- cooperative loads ----
    {
        const float4* lg = (const float4*)g_lut;
        float4* ls = (float4*)sLUT;
        for (int i = tid; i < 512; i += NTHR) ls[i] = lg[i];
    }
    for (int i = tid; i < NF * 28; i += NTHR) sF[i] = 0.f;   // pad lanes
    __syncthreads();
    for (int i = tid; i < NF * 25; i += NTHR) {
        int fi = i / 25, r25 = i - fi * 25;
        sF[fi * 28 + r25] = filt[i];
    }
    for (int i = tid; i < UT * UT; i += NTHR) {    // 1600 logical u cells
        int r = i / UT, c = i - r * UT;
        int gy = oy0 - 4 + r, gx = ox0 - 4 + c;
        float v = 0.f;
        if ((unsigned)gy < IMH && (unsigned)gx < IMW) v = ub[gy * IMW + gx];
        sU[r * RS + c] = v;
    }
    __syncthreads();

    const float invM = s_invM;

    // ---- u_sigma/M on phi tile; zero outside image ----
    for (int i = tid; i < PT * PT; i += NTHR) {
        int r = i / PT, c = i - r * PT;
        int gy = oy0 - 2 + r, gx = ox0 - 2 + c;
        float v = 0.f;
        if ((unsigned)gy < IMH && (unsigned)gx < IMW) {
            float s0 = sU[(r + 1) * RS + c + 1] + sU[(r + 1) * RS + c + 2] + sU[(r + 1) * RS + c + 3];
            float s1 = sU[(r + 2) * RS + c + 1] + sU[(r + 2) * RS + c + 2] + sU[(r + 2) * RS + c + 3];
            float s2 = sU[(r + 3) * RS + c + 1] + sU[(r + 3) * RS + c + 2] + sU[(r + 3) * RS + c + 3];
            v = (s0 + s1 + s2) * (1.f / 9.f) * invM;
        }
        sUS[r * RS + c] = v;
    }
    __syncthreads();

    // ---- per-thread fixed strips ----
    const int ffr0 = (gt / 9) * 3;        // forward: 3x4 strip, 108 active
    const int ffc0 = (gt % 9) * 4;
    const bool fwd_on = (gt < 108);
    const int qr0 = (gt >> 3) * 2;        // adjoint: 2x4 strip, 128 active
    const int qc0 = (gt & 7) * 4;

    float acc[8];
    #pragma unroll
    for (int k = 0; k < 8; k++) acc[k] = 0.f;

    const int fbase = g * NFG;

    #define GBAR() asm volatile("bar.sync %0, %1;" :: "r"(g + 1), "r"(128) : "memory")

    // 20 FMAs: 4 outputs, 5 scalar taps, window (A,B)
    #define ROW_FMA4(D0, D1, D2, D3, A, B, T0, T1, T2, T3, T4)                \
        D0 = fmaf(A.x, T0, D0); D1 = fmaf(A.y, T0, D1);                       \
        D2 = fmaf(A.z, T0, D2); D3 = fmaf(A.w, T0, D3);                       \
        D0 = fmaf(A.y, T1, D0); D1 = fmaf(A.z, T1, D1);                       \
        D2 = fmaf(A.w, T1, D2); D3 = fmaf(B.x, T1, D3);                       \
        D0 = fmaf(A.z, T2, D0); D1 = fmaf(A.w, T2, D1);                       \
        D2 = fmaf(B.x, T2, D2); D3 = fmaf(B.y, T2, D3);                       \
        D0 = fmaf(A.w, T3, D0); D1 = fmaf(B.x, T3, D1);                       \
        D2 = fmaf(B.y, T3, D2); D3 = fmaf(B.z, T3, D3);                       \
        D0 = fmaf(B.x, T4, D0); D1 = fmaf(B.y, T4, D1);                       \
        D2 = fmaf(B.z, T4, D2); D3 = fmaf(B.w, T4, D3);

    #pragma unroll 1
    for (int kf = 0; kf < NFG; kf++) {
        // filter taps into registers: 7 x LDS.128 (broadcast)
        float F[28];
        {
            const float4* Fq = (const float4*)&sF[(fbase + kf) * 28];
            #pragma unroll
            for (int q = 0; q < 7; q++) {
                float4 v = Fq[q];
                F[q * 4 + 0] = v.x; F[q * 4 + 1] = v.y;
                F[q * 4 + 2] = v.z; F[q * 4 + 3] = v.w;
            }
        }

        // ---- forward: dy-major, each of 7 u rows loaded once ----
        if (fwd_on) {
            float a[12];
            #pragma unroll
            for (int k = 0; k < 12; k++) a[k] = 0.f;
            #pragma unroll
            for (int dy = 0; dy < 7; dy++) {
                const float4* rp = (const float4*)&sU[(ffr0 + dy) * RS + ffc0];
                float4 A = rp[0], B = rp[1];
                #pragma unroll
                for (int rr = 0; rr < 3; rr++) {
                    const int ky = dy - rr;
                    if (ky >= 0 && ky <= 4) {
                        ROW_FMA4(a[rr*4+0], a[rr*4+1], a[rr*4+2], a[rr*4+3],
                                 A, B,
                                 F[ky*5+0], F[ky*5+1], F[ky*5+2], F[ky*5+3], F[ky*5+4])
                    }
                }
            }
            #pragma unroll
            for (int rr = 0; rr < 3; rr++) {
                float4 usv = *(const float4*)&sUS[(ffr0 + rr) * RS + ffc0];
                float us[4] = {usv.x, usv.y, usv.z, usv.w};
                float res[4];
                #pragma unroll
                for (int k = 0; k < 4; k++) {
                    float tt = fmaf(a[rr * 4 + k], LUT_INVH, 512.0f);
                    float yy = tt + MAGICF;
                    int ii = __float_as_int(yy) - MAGICI;
                    ii = min(max(ii, 0), NCELL - 1);
                    float frac = tt - (yy - MAGICF);
                    float2 cell = sLUT[ii];
                    res[k] = us[k] * fmaf(cell.y, frac, cell.x);
                }
                *(float4*)&phiBuf[(ffr0 + rr) * RS + ffc0] =
                    make_float4(res[0], res[1], res[2], res[3]);
            }
        }
        GBAR();

        // ---- adjoint: dy-major, each of 6 phi rows loaded once; same F flipped ----
        {
            #pragma unroll
            for (int dy = 0; dy < 6; dy++) {
                const float4* rp = (const float4*)&phiBuf[(qr0 + dy) * RS + qc0];
                float4 A = rp[0], B = rp[1];
                #pragma unroll
                for (int rr = 0; rr < 2; rr++) {
                    const int ky = dy - rr;
                    if (ky >= 0 && ky <= 4) {
                        ROW_FMA4(acc[rr*4+0], acc[rr*4+1], acc[rr*4+2], acc[rr*4+3],
                                 A, B,
                                 F[(4-ky)*5+4], F[(4-ky)*5+3], F[(4-ky)*5+2],
                                 F[(4-ky)*5+1], F[(4-ky)*5+0])
                    }
                }
            }
        }
        GBAR();
    }
    #undef ROW_FMA4
    #undef GBAR

    // ---- combine group accumulators (groups 1,2 -> smem; group 0 sums) ----
    __syncthreads();                 // all groups done with their phi buffers
    if (g > 0) {
        float4* buf = (float4*)(smem + OFF_PHI + g * PHI_STRIDE);
        buf[gt * 2 + 0] = make_float4(acc[0], acc[1], acc[2], acc[3]);
        buf[gt * 2 + 1] = make_float4(acc[4], acc[5], acc[6], acc[7]);
    }
    __syncthreads();

    // ---- epilogue: reaction + clip (group 0) ----
    if (g == 0) {
        #pragma unroll
        for (int gg = 1; gg < 3; gg++) {
            const float4* buf = (const float4*)(smem + OFF_PHI + gg * PHI_STRIDE);
            float4 c0 = buf[gt * 2 + 0], c1 = buf[gt * 2 + 1];
            acc[0] += c0.x; acc[1] += c0.y; acc[2] += c0.z; acc[3] += c0.w;
            acc[4] += c1.x; acc[5] += c1.y; acc[6] += c1.z; acc[7] += c1.w;
        }
        const float lambda = lam[0];
        #pragma unroll
        for (int rr = 0; rr < 2; rr++) {
            const int gy = oy0 + qr0 + rr;
            if (gy < IMH) {
                float4 uv4 = *(const float4*)&sU[(qr0 + rr + 4) * RS + qc0 + 4];
                float uvs[4] = {uv4.x, uv4.y, uv4.z, uv4.w};
                #pragma unroll
                for (int k = 0; k < 4; k++) {
                    int gx = ox0 + qc0 + k;
                    if (gx < IMW) {
                        float uv = uvs[k];
                        float fv = fb[gy * IMW + gx];
                        float reac = lambda * (uv - fv) / (uv * uv + 1e-3f);
                        float o = uv - acc[rr * 4 + k] - reac;
                        o = fminf(fmaxf(o, 0.f), 1.f);
                        ob[gy * IMW + gx] = o;
                    }
                }
            }
        }
    }
}

// ---------------------------------------------------------------------------
// Launch
// ---------------------------------------------------------------------------
extern "C" void kernel_launch(void* const* d_in, const int* in_sizes, int n_in,
                              void* d_out, int out_size) {
    const float* u    = (const float*)d_in[0];
    const float* f    = (const float*)d_in[1];
    const float* filt = (const float*)d_in[2];
    const float* lam  = (const float*)d_in[3];
    const float* mu   = (const float*)d_in[4];
    const float* wts  = (const float*)d_in[5];
    float* out = (float*)d_out;

    k_init<<<68, 256>>>(u, mu, wts);
    dim3 grid((IMW + TILE - 1) / TILE, (IMH + TILE - 1) / TILE, BATCH);
    k_main<<<grid, NTHR, SMEM_BYTES>>>(u, f, filt, lam, out);
}

// round 16
// speedup vs baseline: 1.0661x; 1.0661x over previous
#include <cuda_runtime.h>

// Problem constants
#define BATCH 8
#define IMH 180
#define IMW 180
#define NF 24
#define NB 31
#define NPIX (IMH * IMW)          // 32400
#define NTOT (BATCH * NPIX)       // 259200
#define N4   (NTOT / 4)           // 64800

#define TILE 32
#define UT 40                      // u tile rows (TILE + 2*4)
#define PT 36                      // phi tile rows (TILE + 2*2)
#define RS 44                      // padded row stride (words): conflict-free phases

// LUT for phi(x); nearest-knot + centered slope, magic-number index
#define NCELL 1024
#define XMIN (-2.0f)
#define XMAX (2.0f)
#define LUT_H ((XMAX - XMIN) / (float)NCELL)
#define LUT_INVH ((float)NCELL / (XMAX - XMIN))
#define MAGICF 12582912.0f         // 1.5 * 2^23
#define MAGICI 0x4B400000

#define NTHR 384                   // 3 filter-groups of 128 threads
#define NFG  8                     // filters per group
#define NCTA 288                   // 6 x 6 x 8 grid — all co-resident at occ 2

__device__ unsigned long long g_ticket;   // monotonic; replay-safe
__device__ float  g_part2[NCTA];
__device__ float2 g_lut[NCELL];

// ---------------------------------------------------------------------------
// k_main: single fused kernel. Phase 1: per-CTA weighted u-sum partial +
// distributed LUT build (overlapped with sU/sF smem loads). Grid-wide
// ticket-spin barrier (all 288 CTAs co-resident at occupancy 2). Phase 2:
// reduce partials -> invM, load LUT, then the R15 filter loop:
// 3 groups x 128 thr; per filter F[25] in regs (7 LDS.128), FWD dy-major
// (7 u rows loaded once) ; bar ; ADJ dy-major (6 phi rows once, F flipped).
// Dynamic smem layout (bytes):
//   [0, 8192)        sLUT : 1024 x float2
//   [8192, 15232)    sU   : 40 rows x 44 stride
//   [15232, 21568)   sUS  : 36 rows x 44 stride
//   [21568, 40576)   sPhi : 3 buffers of 36 x 44 (one per group)
//   [40576, 43264)   sF   : 24 filters x 28 floats (25 taps + 3 pad)
// ---------------------------------------------------------------------------
#define OFF_LUT 0
#define OFF_U   8192
#define OFF_US  15232
#define OFF_PHI 21568
#define OFF_F   40576
#define PHI_STRIDE (PT * RS * 4)   // 6336 bytes
#define SMEM_BYTES 43264

__global__ __launch_bounds__(NTHR, 2) void k_main(
    const float* __restrict__ u,
    const float* __restrict__ f,
    const float* __restrict__ filt,
    const float* __restrict__ lam,
    const float* __restrict__ mu,
    const float* __restrict__ wts,
    float* __restrict__ out)
{
    extern __shared__ char smem[];
    float2* sLUT = (float2*)(smem + OFF_LUT);
    float*  sU   = (float*)(smem + OFF_U);
    float*  sUS  = (float*)(smem + OFF_US);
    float*  sF   = (float*)(smem + OFF_F);
    __shared__ float s_red[256];
    __shared__ float s_invM;
    __shared__ unsigned long long s_tk;

    const int b   = blockIdx.z;
    const int oy0 = blockIdx.y * TILE;
    const int ox0 = blockIdx.x * TILE;
    const int tid = threadIdx.x;
    const int g   = tid / 128;         // filter-group 0..2
    const int gt  = tid - g * 128;     // lane within group
    const int bid = (blockIdx.z * gridDim.y + blockIdx.y) * gridDim.x + blockIdx.x;

    const float* ub = u + b * NPIX;
    const float* fb = f + b * NPIX;
    float* ob = out + b * NPIX;

    float* phiBuf = (float*)(smem + OFF_PHI + g * PHI_STRIDE);

    // ======== Phase 1a: per-CTA partial of weighted u-sum (225 float4) ====
    {
        float s = 0.f;
        if (tid < 225) {
            int i = bid * 225 + tid;           // < N4 = 64800 = 288*225
            int idx4 = i * 4;
            int p = idx4 % NPIX;
            int y = p / IMW;
            int x0 = p - y * IMW;
            float wy = 3.f - (y == 0 ? 1.f : 0.f) - (y == IMH - 1 ? 1.f : 0.f);
            float4 v = ((const float4*)u)[i];
            float w0 = (x0 == 0) ? 2.f : 3.f;
            float w3 = (x0 == IMW - 4) ? 2.f : 3.f;
            s = wy * (v.x * w0 + v.y * 3.f + v.z * 3.f + v.w * w3);
        }
        if (tid < 256) s_red[tid] = s;
        // Phase 1b: CTAs < 256 build 4 LUT cells each (threads 256..259)
        if (bid < 256 && tid >= 256 && tid < 260) {
            int i = bid * 4 + (tid - 256);     // 0..1023
            float xc = XMIN + (float)i * LUT_H;
            float pm = 0.f, p0 = 0.f, pp = 0.f;
            #pragma unroll 1
            for (int j = 0; j < NB; j++) {
                float m = mu[j], w = wts[j];
                float dm = xc - LUT_H - m, d0 = xc - m, dp = xc + LUT_H - m;
                pm += w * expf(-50.f * dm * dm);
                p0 += w * expf(-50.f * d0 * d0);
                pp += w * expf(-50.f * dp * dp);
            }
            g_lut[i] = make_float2(p0, 0.5f * (pp - pm));
        }
        __syncthreads();
        for (int o = 128; o > 0; o >>= 1) {
            if (tid < o) s_red[tid] += s_red[tid + o];
            __syncthreads();
        }
        if (tid == 0) {
            g_part2[bid] = s_red[0];
            __threadfence();
            s_tk = atomicAdd(&g_ticket, 1ULL);
        }
    }

    // ======== Phase 1c: overlap smem loads that don't need M/LUT =========
    for (int i = tid; i < NF * 28; i += NTHR) sF[i] = 0.f;   // pad lanes
    __syncthreads();
    for (int i = tid; i < NF * 25; i += NTHR) {
        int fi = i / 25, r25 = i - fi * 25;
        sF[fi * 28 + r25] = filt[i];
    }
    for (int i = tid; i < UT * UT; i += NTHR) {    // 1600 logical u cells
        int r = i / UT, c = i - r * UT;
        int gy = oy0 - 4 + r, gx = ox0 - 4 + c;
        float v = 0.f;
        if ((unsigned)gy < IMH && (unsigned)gx < IMW) v = ub[gy * IMW + gx];
        sU[r * RS + c] = v;
    }
    __syncthreads();

    // ======== Grid-wide spin barrier =====================================
    if (tid == 0) {
        unsigned long long target = (s_tk / NCTA + 1ULL) * NCTA;
        volatile unsigned long long* tp = &g_ticket;
        while (*tp < target) { }
    }
    __syncthreads();
    __threadfence();

    // ======== Phase 2: LUT to smem, invM, sUS ============================
    {
        const float4* lg = (const float4*)g_lut;
        float4* ls = (float4*)sLUT;
        for (int i = tid; i < 512; i += NTHR) ls[i] = lg[i];
    }
    if (tid < 32) {
        float s = 0.f;
        #pragma unroll
        for (int j = 0; j < 9; j++)        // 288 = 9 * 32, fixed order
            s += g_part2[tid + 32 * j];
        #pragma unroll
        for (int o = 16; o > 0; o >>= 1)
            s += __shfl_down_sync(0xffffffffu, s, o);
        if (tid == 0)
            s_invM = 1.f / (s / (9.f * (float)NTOT) + 0.001f);
    }
    __syncthreads();
    const float invM = s_invM;

    for (int i = tid; i < PT * PT; i += NTHR) {
        int r = i / PT, c = i - r * PT;
        int gy = oy0 - 2 + r, gx = ox0 - 2 + c;
        float v = 0.f;
        if ((unsigned)gy < IMH && (unsigned)gx < IMW) {
            float s0 = sU[(r + 1) * RS + c + 1] + sU[(r + 1) * RS + c + 2] + sU[(r + 1) * RS + c + 3];
            float s1 = sU[(r + 2) * RS + c + 1] + sU[(r + 2) * RS + c + 2] + sU[(r + 2) * RS + c + 3];
            float s2 = sU[(r + 3) * RS + c + 1] + sU[(r + 3) * RS + c + 2] + sU[(r + 3) * RS + c + 3];
            v = (s0 + s1 + s2) * (1.f / 9.f) * invM;
        }
        sUS[r * RS + c] = v;
    }
    __syncthreads();

    // ---- per-thread fixed strips ----
    const int ffr0 = (gt / 9) * 3;        // forward: 3x4 strip, 108 active
    const int ffc0 = (gt % 9) * 4;
    const bool fwd_on = (gt < 108);
    const int qr0 = (gt >> 3) * 2;        // adjoint: 2x4 strip, 128 active
    const int qc0 = (gt & 7) * 4;

    float acc[8];
    #pragma unroll
    for (int k = 0; k < 8; k++) acc[k] = 0.f;

    const int fbase = g * NFG;

    #define GBAR() asm volatile("bar.sync %0, %1;" :: "r"(g + 1), "r"(128) : "memory")

    #define ROW_FMA4(D0, D1, D2, D3, A, B, T0, T1, T2, T3, T4)                \
        D0 = fmaf(A.x, T0, D0); D1 = fmaf(A.y, T0, D1);                       \
        D2 = fmaf(A.z, T0, D2); D3 = fmaf(A.w, T0, D3);                       \
        D0 = fmaf(A.y, T1, D0); D1 = fmaf(A.z, T1, D1);                       \
        D2 = fmaf(A.w, T1, D2); D3 = fmaf(B.x, T1, D3);                       \
        D0 = fmaf(A.z, T2, D0); D1 = fmaf(A.w, T2, D1);                       \
        D2 = fmaf(B.x, T2, D2); D3 = fmaf(B.y, T2, D3);                       \
        D0 = fmaf(A.w, T3, D0); D1 = fmaf(B.x, T3, D1);                       \
        D2 = fmaf(B.y, T3, D2); D3 = fmaf(B.z, T3, D3);                       \
        D0 = fmaf(B.x, T4, D0); D1 = fmaf(B.y, T4, D1);                       \
        D2 = fmaf(B.z, T4, D2); D3 = fmaf(B.w, T4, D3);

    #pragma unroll 1
    for (int kf = 0; kf < NFG; kf++) {
        float F[28];
        {
            const float4* Fq = (const float4*)&sF[(fbase + kf) * 28];
            #pragma unroll
            for (int q = 0; q < 7; q++) {
                float4 v = Fq[q];
                F[q * 4 + 0] = v.x; F[q * 4 + 1] = v.y;
                F[q * 4 + 2] = v.z; F[q * 4 + 3] = v.w;
            }
        }

        if (fwd_on) {
            float a[12];
            #pragma unroll
            for (int k = 0; k < 12; k++) a[k] = 0.f;
            #pragma unroll
            for (int dy = 0; dy < 7; dy++) {
                const float4* rp = (const float4*)&sU[(ffr0 + dy) * RS + ffc0];
                float4 A = rp[0], B = rp[1];
                #pragma unroll
                for (int rr = 0; rr < 3; rr++) {
                    const int ky = dy - rr;
                    if (ky >= 0 && ky <= 4) {
                        ROW_FMA4(a[rr*4+0], a[rr*4+1], a[rr*4+2], a[rr*4+3],
                                 A, B,
                                 F[ky*5+0], F[ky*5+1], F[ky*5+2], F[ky*5+3], F[ky*5+4])
                    }
                }
            }
            #pragma unroll
            for (int rr = 0; rr < 3; rr++) {
                float4 usv = *(const float4*)&sUS[(ffr0 + rr) * RS + ffc0];
                float us[4] = {usv.x, usv.y, usv.z, usv.w};
                float res[4];
                #pragma unroll
                for (int k = 0; k < 4; k++) {
                    float tt = fmaf(a[rr * 4 + k], LUT_INVH, 512.0f);
                    float yy = tt + MAGICF;
                    int ii = __float_as_int(yy) - MAGICI;
                    ii = min(max(ii, 0), NCELL - 1);
                    float frac = tt - (yy - MAGICF);
                    float2 cell = sLUT[ii];
                    res[k] = us[k] * fmaf(cell.y, frac, cell.x);
                }
                *(float4*)&phiBuf[(ffr0 + rr) * RS + ffc0] =
                    make_float4(res[0], res[1], res[2], res[3]);
            }
        }
        GBAR();

        {
            #pragma unroll
            for (int dy = 0; dy < 6; dy++) {
                const float4* rp = (const float4*)&phiBuf[(qr0 + dy) * RS + qc0];
                float4 A = rp[0], B = rp[1];
                #pragma unroll
                for (int rr = 0; rr < 2; rr++) {
                    const int ky = dy - rr;
                    if (ky >= 0 && ky <= 4) {
                        ROW_FMA4(acc[rr*4+0], acc[rr*4+1], acc[rr*4+2], acc[rr*4+3],
                                 A, B,
                                 F[(4-ky)*5+4], F[(4-ky)*5+3], F[(4-ky)*5+2],
                                 F[(4-ky)*5+1], F[(4-ky)*5+0])
                    }
                }
            }
        }
        GBAR();
    }
    #undef ROW_FMA4
    #undef GBAR

    // ---- combine group accumulators (groups 1,2 -> smem; group 0 sums) ----
    __syncthreads();
    if (g > 0) {
        float4* buf = (float4*)(smem + OFF_PHI + g * PHI_STRIDE);
        buf[gt * 2 + 0] = make_float4(acc[0], acc[1], acc[2], acc[3]);
        buf[gt * 2 + 1] = make_float4(acc[4], acc[5], acc[6], acc[7]);
    }
    __syncthreads();

    // ---- epilogue: reaction + clip (group 0) ----
    if (g == 0) {
        #pragma unroll
        for (int gg = 1; gg < 3; gg++) {
            const float4* buf = (const float4*)(smem + OFF_PHI + gg * PHI_STRIDE);
            float4 c0 = buf[gt * 2 + 0], c1 = buf[gt * 2 + 1];
            acc[0] += c0.x; acc[1] += c0.y; acc[2] += c0.z; acc[3] += c0.w;
            acc[4] += c1.x; acc[5] += c1.y; acc[6] += c1.z; acc[7] += c1.w;
        }
        const float lambda = lam[0];
        #pragma unroll
        for (int rr = 0; rr < 2; rr++) {
            const int gy = oy0 + qr0 + rr;
            if (gy < IMH) {
                float4 uv4 = *(const float4*)&sU[(qr0 + rr + 4) * RS + qc0 + 4];
                float uvs[4] = {uv4.x, uv4.y, uv4.z, uv4.w};
                #pragma unroll
                for (int k = 0; k < 4; k++) {
                    int gx = ox0 + qc0 + k;
                    if (gx < IMW) {
                        float uv = uvs[k];
                        float fv = fb[gy * IMW + gx];
                        float reac = lambda * (uv - fv) / (uv * uv + 1e-3f);
                        float o = uv - acc[rr * 4 + k] - reac;
                        o = fminf(fmaxf(o, 0.f), 1.f);
                        ob[gy * IMW + gx] = o;
                    }
                }
            }
        }
    }
}

// ---------------------------------------------------------------------------
// Launch: ONE kernel. All 288 CTAs are co-resident (occupancy 2 x 148 SMs),
// so the in-kernel ticket barrier cannot deadlock.
// ---------------------------------------------------------------------------
extern "C" void kernel_launch(void* const* d_in, const int* in_sizes, int n_in,
                              void* d_out, int out_size) {
    const float* u    = (const float*)d_in[0];
    const float* f    = (const float*)d_in[1];
    const float* filt = (const float*)d_in[2];
    const float* lam  = (const float*)d_in[3];
    const float* mu   = (const float*)d_in[4];
    const float* wts  = (const float*)d_in[5];
    float* out = (float*)d_out;

    dim3 grid((IMW + TILE - 1) / TILE, (IMH + TILE - 1) / TILE, BATCH);  // 6x6x8
    k_main<<<grid, NTHR, SMEM_BYTES>>>(u, f, filt, lam, mu, wts, out);
}

// round 17
// speedup vs baseline: 1.0671x; 1.0009x over previous
#include <cuda_runtime.h>

// Problem constants
#define BATCH 8
#define IMH 180
#define IMW 180
#define NF 24
#define NB 31
#define NPIX (IMH * IMW)          // 32400
#define NTOT (BATCH * NPIX)       // 259200
#define N4   (NTOT / 4)           // 64800

#define TILE 32
#define UT 40                      // u tile rows (TILE + 2*4)
#define PT 36                      // phi tile rows (TILE + 2*2)
#define RS 44                      // padded row stride (words): conflict-free phases

// LUT for phi(x); nearest-knot + centered slope, magic-number index
#define NCELL 1024
#define XMIN (-2.0f)
#define XMAX (2.0f)
#define LUT_H ((XMAX - XMIN) / (float)NCELL)
#define LUT_INVH ((float)NCELL / (XMAX - XMIN))
#define MAGICF 12582912.0f         // 1.5 * 2^23
#define MAGICI 0x4B400000

#define NTHR 384                   // 3 filter-groups of 128 threads
#define NFG  8                     // filters per group
#define NCTA 288                   // 6 x 6 x 8 grid — all co-resident at occ 2

__device__ unsigned long long g_ticket;   // monotonic; replay-safe
__device__ float  g_part2[NCTA];
__device__ float2 g_lut[NCELL];

// ---------------------------------------------------------------------------
// k_main: single fused kernel (grid-wide ticket barrier; 288 CTAs co-resident
// at occupancy 2). Filter loop: rotated pipeline with ONE barrier per filter:
//   loadF(k); FWD(k) -> buf[k&1]; bar; ADJ(k) <- buf[k&1]
// Double phi buffers per group make FWD(k+1) race-free against ADJ(k-1)
// (separated by bar(k)), and ADJ(k) || FWD(k+1) share an issue window.
// Dynamic smem layout (bytes):
//   [0, 8192)        sLUT : 1024 x float2
//   [8192, 15232)    sU   : 40 rows x 44 stride
//   [15232, 21568)   sUS  : 36 rows x 44 stride
//   [21568, 59584)   sPhi : 6 buffers of 36 x 44 (2 per group)
//   [59584, 62272)   sF   : 24 filters x 28 floats (25 taps + 3 pad)
// ---------------------------------------------------------------------------
#define OFF_LUT 0
#define OFF_U   8192
#define OFF_US  15232
#define OFF_PHI 21568
#define OFF_F   59584
#define PHI_STRIDE (PT * RS * 4)   // 6336 bytes
#define SMEM_BYTES 62272

__global__ __launch_bounds__(NTHR, 2) void k_main(
    const float* __restrict__ u,
    const float* __restrict__ f,
    const float* __restrict__ filt,
    const float* __restrict__ lam,
    const float* __restrict__ mu,
    const float* __restrict__ wts,
    float* __restrict__ out)
{
    extern __shared__ char smem[];
    float2* sLUT = (float2*)(smem + OFF_LUT);
    float*  sU   = (float*)(smem + OFF_U);
    float*  sUS  = (float*)(smem + OFF_US);
    float*  sF   = (float*)(smem + OFF_F);
    __shared__ float s_red[256];
    __shared__ float s_invM;
    __shared__ unsigned long long s_tk;

    const int b   = blockIdx.z;
    const int oy0 = blockIdx.y * TILE;
    const int ox0 = blockIdx.x * TILE;
    const int tid = threadIdx.x;
    const int g   = tid / 128;         // filter-group 0..2
    const int gt  = tid - g * 128;     // lane within group
    const int bid = (blockIdx.z * gridDim.y + blockIdx.y) * gridDim.x + blockIdx.x;

    const float* ub = u + b * NPIX;
    const float* fb = f + b * NPIX;
    float* ob = out + b * NPIX;

    float* phiBuf[2] = { (float*)(smem + OFF_PHI + (2 * g + 0) * PHI_STRIDE),
                         (float*)(smem + OFF_PHI + (2 * g + 1) * PHI_STRIDE) };

    // ======== Phase 1a: per-CTA partial of weighted u-sum (225 float4) ====
    {
        float s = 0.f;
        if (tid < 225) {
            int i = bid * 225 + tid;           // < N4 = 64800 = 288*225
            int idx4 = i * 4;
            int p = idx4 % NPIX;
            int y = p / IMW;
            int x0 = p - y * IMW;
            float wy = 3.f - (y == 0 ? 1.f : 0.f) - (y == IMH - 1 ? 1.f : 0.f);
            float4 v = ((const float4*)u)[i];
            float w0 = (x0 == 0) ? 2.f : 3.f;
            float w3 = (x0 == IMW - 4) ? 2.f : 3.f;
            s = wy * (v.x * w0 + v.y * 3.f + v.z * 3.f + v.w * w3);
        }
        if (tid < 256) s_red[tid] = s;
        // Phase 1b: CTAs < 256 build 4 LUT cells each (threads 256..259)
        if (bid < 256 && tid >= 256 && tid < 260) {
            int i = bid * 4 + (tid - 256);     // 0..1023
            float xc = XMIN + (float)i * LUT_H;
            float pm = 0.f, p0 = 0.f, pp = 0.f;
            #pragma unroll 1
            for (int j = 0; j < NB; j++) {
                float m = mu[j], w = wts[j];
                float dm = xc - LUT_H - m, d0 = xc - m, dp = xc + LUT_H - m;
                pm += w * expf(-50.f * dm * dm);
                p0 += w * expf(-50.f * d0 * d0);
                pp += w * expf(-50.f * dp * dp);
            }
            g_lut[i] = make_float2(p0, 0.5f * (pp - pm));
        }
        __syncthreads();
        for (int o = 128; o > 0; o >>= 1) {
            if (tid < o) s_red[tid] += s_red[tid + o];
            __syncthreads();
        }
        if (tid == 0) {
            g_part2[bid] = s_red[0];
            __threadfence();
            s_tk = atomicAdd(&g_ticket, 1ULL);
        }
    }

    // ======== Phase 1c: overlap smem loads that don't need M/LUT =========
    for (int i = tid; i < NF * 28; i += NTHR) sF[i] = 0.f;   // pad lanes
    __syncthreads();
    for (int i = tid; i < NF * 25; i += NTHR) {
        int fi = i / 25, r25 = i - fi * 25;
        sF[fi * 28 + r25] = filt[i];
    }
    for (int i = tid; i < UT * UT; i += NTHR) {    // 1600 logical u cells
        int r = i / UT, c = i - r * UT;
        int gy = oy0 - 4 + r, gx = ox0 - 4 + c;
        float v = 0.f;
        if ((unsigned)gy < IMH && (unsigned)gx < IMW) v = ub[gy * IMW + gx];
        sU[r * RS + c] = v;
    }
    __syncthreads();

    // ======== Grid-wide spin barrier =====================================
    if (tid == 0) {
        unsigned long long target = (s_tk / NCTA + 1ULL) * NCTA;
        volatile unsigned long long* tp = &g_ticket;
        while (*tp < target) { }
    }
    __syncthreads();
    __threadfence();

    // ======== Phase 2: LUT to smem, invM, sUS ============================
    {
        const float4* lg = (const float4*)g_lut;
        float4* ls = (float4*)sLUT;
        for (int i = tid; i < 512; i += NTHR) ls[i] = lg[i];
    }
    if (tid < 32) {
        float s = 0.f;
        #pragma unroll
        for (int j = 0; j < 9; j++)        // 288 = 9 * 32, fixed order
            s += g_part2[tid + 32 * j];
        #pragma unroll
        for (int o = 16; o > 0; o >>= 1)
            s += __shfl_down_sync(0xffffffffu, s, o);
        if (tid == 0)
            s_invM = 1.f / (s / (9.f * (float)NTOT) + 0.001f);
    }
    __syncthreads();
    const float invM = s_invM;

    for (int i = tid; i < PT * PT; i += NTHR) {
        int r = i / PT, c = i - r * PT;
        int gy = oy0 - 2 + r, gx = ox0 - 2 + c;
        float v = 0.f;
        if ((unsigned)gy < IMH && (unsigned)gx < IMW) {
            float s0 = sU[(r + 1) * RS + c + 1] + sU[(r + 1) * RS + c + 2] + sU[(r + 1) * RS + c + 3];
            float s1 = sU[(r + 2) * RS + c + 1] + sU[(r + 2) * RS + c + 2] + sU[(r + 2) * RS + c + 3];
            float s2 = sU[(r + 3) * RS + c + 1] + sU[(r + 3) * RS + c + 2] + sU[(r + 3) * RS + c + 3];
            v = (s0 + s1 + s2) * (1.f / 9.f) * invM;
        }
        sUS[r * RS + c] = v;
    }
    __syncthreads();

    // ---- per-thread fixed strips ----
    const int ffr0 = (gt / 9) * 3;        // forward: 3x4 strip, 108 active
    const int ffc0 = (gt % 9) * 4;
    const bool fwd_on = (gt < 108);
    const int qr0 = (gt >> 3) * 2;        // adjoint: 2x4 strip, 128 active
    const int qc0 = (gt & 7) * 4;

    float acc[8];
    #pragma unroll
    for (int k = 0; k < 8; k++) acc[k] = 0.f;

    const int fbase = g * NFG;

    #define GBAR() asm volatile("bar.sync %0, %1;" :: "r"(g + 1), "r"(128) : "memory")

    #define ROW_FMA4(D0, D1, D2, D3, A, B, T0, T1, T2, T3, T4)                \
        D0 = fmaf(A.x, T0, D0); D1 = fmaf(A.y, T0, D1);                       \
        D2 = fmaf(A.z, T0, D2); D3 = fmaf(A.w, T0, D3);                       \
        D0 = fmaf(A.y, T1, D0); D1 = fmaf(A.z, T1, D1);                       \
        D2 = fmaf(A.w, T1, D2); D3 = fmaf(B.x, T1, D3);                       \
        D0 = fmaf(A.z, T2, D0); D1 = fmaf(A.w, T2, D1);                       \
        D2 = fmaf(B.x, T2, D2); D3 = fmaf(B.y, T2, D3);                       \
        D0 = fmaf(A.w, T3, D0); D1 = fmaf(B.x, T3, D1);                       \
        D2 = fmaf(B.y, T3, D2); D3 = fmaf(B.z, T3, D3);                       \
        D0 = fmaf(B.x, T4, D0); D1 = fmaf(B.y, T4, D1);                       \
        D2 = fmaf(B.z, T4, D2); D3 = fmaf(B.w, T4, D3);

    // Rotated pipeline: loadF(k); FWD(k)->buf[k&1]; bar; ADJ(k)<-buf[k&1].
    // FWD(k+1) is separated from ADJ(k-1) (last reader of buf[(k+1)&1])
    // by bar(k); ADJ(k) reads what FWD(k) wrote before bar(k).
    #pragma unroll 1
    for (int kf = 0; kf < NFG; kf++) {
        float F[28];
        {
            const float4* Fq = (const float4*)&sF[(fbase + kf) * 28];
            #pragma unroll
            for (int q = 0; q < 7; q++) {
                float4 v = Fq[q];
                F[q * 4 + 0] = v.x; F[q * 4 + 1] = v.y;
                F[q * 4 + 2] = v.z; F[q * 4 + 3] = v.w;
            }
        }
        float* bufW = phiBuf[kf & 1];

        if (fwd_on) {
            float a[12];
            #pragma unroll
            for (int k = 0; k < 12; k++) a[k] = 0.f;
            #pragma unroll
            for (int dy = 0; dy < 7; dy++) {
                const float4* rp = (const float4*)&sU[(ffr0 + dy) * RS + ffc0];
                float4 A = rp[0], B = rp[1];
                #pragma unroll
                for (int rr = 0; rr < 3; rr++) {
                    const int ky = dy - rr;
                    if (ky >= 0 && ky <= 4) {
                        ROW_FMA4(a[rr*4+0], a[rr*4+1], a[rr*4+2], a[rr*4+3],
                                 A, B,
                                 F[ky*5+0], F[ky*5+1], F[ky*5+2], F[ky*5+3], F[ky*5+4])
                    }
                }
            }
            #pragma unroll
            for (int rr = 0; rr < 3; rr++) {
                float4 usv = *(const float4*)&sUS[(ffr0 + rr) * RS + ffc0];
                float us[4] = {usv.x, usv.y, usv.z, usv.w};
                float res[4];
                #pragma unroll
                for (int k = 0; k < 4; k++) {
                    float tt = fmaf(a[rr * 4 + k], LUT_INVH, 512.0f);
                    float yy = tt + MAGICF;
                    int ii = __float_as_int(yy) - MAGICI;
                    ii = min(max(ii, 0), NCELL - 1);
                    float frac = tt - (yy - MAGICF);
                    float2 cell = sLUT[ii];
                    res[k] = us[k] * fmaf(cell.y, frac, cell.x);
                }
                *(float4*)&bufW[(ffr0 + rr) * RS + ffc0] =
                    make_float4(res[0], res[1], res[2], res[3]);
            }
        }
        GBAR();

        {
            #pragma unroll
            for (int dy = 0; dy < 6; dy++) {
                const float4* rp = (const float4*)&bufW[(qr0 + dy) * RS + qc0];
                float4 A = rp[0], B = rp[1];
                #pragma unroll
                for (int rr = 0; rr < 2; rr++) {
                    const int ky = dy - rr;
                    if (ky >= 0 && ky <= 4) {
                        ROW_FMA4(acc[rr*4+0], acc[rr*4+1], acc[rr*4+2], acc[rr*4+3],
                                 A, B,
                                 F[(4-ky)*5+4], F[(4-ky)*5+3], F[(4-ky)*5+2],
                                 F[(4-ky)*5+1], F[(4-ky)*5+0])
                    }
                }
            }
        }
    }
    #undef ROW_FMA4
    #undef GBAR

    // ---- combine group accumulators (groups 1,2 -> smem; group 0 sums) ----
    __syncthreads();                 // all groups done with their phi buffers
    if (g > 0) {
        float4* buf = (float4*)(smem + OFF_PHI + (2 * g) * PHI_STRIDE);
        buf[gt * 2 + 0] = make_float4(acc[0], acc[1], acc[2], acc[3]);
        buf[gt * 2 + 1] = make_float4(acc[4], acc[5], acc[6], acc[7]);
    }
    __syncthreads();

    // ---- epilogue: reaction + clip (group 0) ----
    if (g == 0) {
        #pragma unroll
        for (int gg = 1; gg < 3; gg++) {
            const float4* buf = (const float4*)(smem + OFF_PHI + (2 * gg) * PHI_STRIDE);
            float4 c0 = buf[gt * 2 + 0], c1 = buf[gt * 2 + 1];
            acc[0] += c0.x; acc[1] += c0.y; acc[2] += c0.z; acc[3] += c0.w;
            acc[4] += c1.x; acc[5] += c1.y; acc[6] += c1.z; acc[7] += c1.w;
        }
        const float lambda = lam[0];
        #pragma unroll
        for (int rr = 0; rr < 2; rr++) {
            const int gy = oy0 + qr0 + rr;
            if (gy < IMH) {
                float4 uv4 = *(const float4*)&sU[(qr0 + rr + 4) * RS + qc0 + 4];
                float uvs[4] = {uv4.x, uv4.y, uv4.z, uv4.w};
                #pragma unroll
                for (int k = 0; k < 4; k++) {
                    int gx = ox0 + qc0 + k;
                    if (gx < IMW) {
                        float uv = uvs[k];
                        float fv = fb[gy * IMW + gx];
                        float reac = lambda * (uv - fv) / (uv * uv + 1e-3f);
                        float o = uv - acc[rr * 4 + k] - reac;
                        o = fminf(fmaxf(o, 0.f), 1.f);
                        ob[gy * IMW + gx] = o;
                    }
                }
            }
        }
    }
}

// ---------------------------------------------------------------------------
// Launch: ONE kernel. All 288 CTAs co-resident (occ 2 x 148 SMs) -> the
// in-kernel ticket barrier cannot deadlock. SMEM > 48KB needs the opt-in
// attribute (set during the pre-capture correctness call).
// ---------------------------------------------------------------------------
extern "C" void kernel_launch(void* const* d_in, const int* in_sizes, int n_in,
                              void* d_out, int out_size) {
    const float* u    = (const float*)d_in[0];
    const float* f    = (const float*)d_in[1];
    const float* filt = (const float*)d_in[2];
    const float* lam  = (const float*)d_in[3];
    const float* mu   = (const float*)d_in[4];
    const float* wts  = (const float*)d_in[5];
    float* out = (float*)d_out;

    static bool attr_set = false;
    if (!attr_set) {
        cudaFuncSetAttribute(k_main, cudaFuncAttributeMaxDynamicSharedMemorySize,
                             SMEM_BYTES);
        attr_set = true;
    }

    dim3 grid((IMW + TILE - 1) / TILE, (IMH + TILE - 1) / TILE, BATCH);  // 6x6x8
    k_main<<<grid, NTHR, SMEM_BYTES>>>(u, f, filt, lam, mu, wts, out);
}